// round 7
// baseline (speedup 1.0000x reference)
#include <cuda_runtime.h>
#include <cuda_fp16.h>
#include <cstdint>

#define N_NODES 200000
#define SEGS    16384
#define NTILES  ((N_NODES + 127) / 128)   // 1563
#define HEADS   4
#define LH2     68     // smem row stride in half2 units
#define LOUT    132    // f32 out-tile stride
#define SLOPE   0.01f

// ---------------- device scratch ----------------
__device__ float    g_alpha[N_NODES * HEADS];
__device__ float    g_e[N_NODES * HEADS];
__device__ unsigned g_amax[SEGS * HEADS];
__device__ float    g_denom[SEGS * HEADS];
__device__ unsigned g_pre1[HEADS * SEGS * 64];   // fp16x2: W1R . cry  per segment

// ---------------- helpers ----------------
__device__ __forceinline__ unsigned h2pack(float a, float b) {
    unsigned r;
    asm("cvt.rn.f16x2.f32 %0, %2, %1;" : "=r"(r) : "f"(a), "f"(b));
    return r;  // lo = a, hi = b
}

__device__ __forceinline__ void mma_f16(float c[4], const unsigned a[4], const unsigned b[2]) {
    asm volatile(
        "mma.sync.aligned.m16n8k16.row.col.f32.f16.f16.f32 "
        "{%0,%1,%2,%3}, {%4,%5,%6,%7}, {%8,%9}, {%0,%1,%2,%3};\n"
        : "+f"(c[0]), "+f"(c[1]), "+f"(c[2]), "+f"(c[3])
        : "r"(a[0]), "r"(a[1]), "r"(a[2]), "r"(a[3]), "r"(b[0]), "r"(b[1]));
}

__device__ __forceinline__ void cpa16(unsigned saddr, const void* g) {
    asm volatile("cp.async.ca.shared.global [%0], [%1], 16;" :: "r"(saddr), "l"(g) : "memory");
}

// 128x128x128 GEMM: C[r][o] += sum_k A[r][k]*B[o][k]; fp16 half2-packed smem,
// row stride LH2. 8 warps (4x2), warp tile 32x64. (R3-proven scalar-LDS feed.)
__device__ __forceinline__ void gemm128h(const unsigned* sA, const unsigned* sB,
                                         float (&acc)[2][8][4],
                                         int warpRow, int warpCol, int g, int t) {
#pragma unroll 4
    for (int ks = 0; ks < 8; ks++) {
        const int k0 = ks * 8;
        unsigned a[2][4], b[8][2];
#pragma unroll
        for (int mt = 0; mt < 2; mt++) {
            int r = warpRow * 32 + mt * 16 + g;
            a[mt][0] = sA[r * LH2 + k0 + t];
            a[mt][1] = sA[(r + 8) * LH2 + k0 + t];
            a[mt][2] = sA[r * LH2 + k0 + t + 4];
            a[mt][3] = sA[(r + 8) * LH2 + k0 + t + 4];
        }
#pragma unroll
        for (int nt = 0; nt < 8; nt++) {
            int o = warpCol * 64 + nt * 8 + g;
            b[nt][0] = sB[o * LH2 + k0 + t];
            b[nt][1] = sB[o * LH2 + k0 + t + 4];
        }
#pragma unroll
        for (int mt = 0; mt < 2; mt++)
#pragma unroll
            for (int nt = 0; nt < 8; nt++)
                mma_f16(acc[mt][nt], a[mt], b[nt]);
    }
}

// load [rows<=128,128] f32 -> fp16 smem tile (256 threads)
__device__ __forceinline__ void load_rows_h(unsigned* dst, const float* __restrict__ src,
                                            int rows, int tid) {
#pragma unroll
    for (int i = 0; i < 16; i++) {
        int v = i * 256 + tid;
        int r = v >> 5, c4 = v & 31;
        float4 val = make_float4(0.f, 0.f, 0.f, 0.f);
        if (r < rows) val = reinterpret_cast<const float4*>(src)[r * 32 + c4];
        uint2 u = make_uint2(h2pack(val.x, val.y), h2pack(val.z, val.w));
        *reinterpret_cast<uint2*>(dst + r * LH2 + c4 * 2) = u;
    }
}

__device__ __forceinline__ void load_w_h(unsigned* dst, const float* __restrict__ src,
                                         int srcStride, int tid) {
#pragma unroll
    for (int i = 0; i < 16; i++) {
        int v = i * 256 + tid;
        int r = v >> 5, c4 = v & 31;
        float4 val = *reinterpret_cast<const float4*>(src + (size_t)r * srcStride + c4 * 4);
        uint2 u = make_uint2(h2pack(val.x, val.y), h2pack(val.z, val.w));
        *reinterpret_cast<uint2*>(dst + r * LH2 + c4 * 2) = u;
    }
}

// ---------------- kernel 0: init ----------------
__global__ void k_init(float* __restrict__ out, int out_size) {
    int i = blockIdx.x * blockDim.x + threadIdx.x;
    int stride = gridDim.x * blockDim.x;
    int n4 = out_size >> 2;
    for (int j = i; j < n4; j += stride)
        reinterpret_cast<float4*>(out)[j] = make_float4(0.f, 0.f, 0.f, 0.f);
    for (int j = n4 * 4 + i; j < out_size; j += stride) out[j] = 0.f;
    for (int j = i; j < SEGS * HEADS; j += stride) {
        g_amax[j] = 0u;
        g_denom[j] = 0.f;
    }
}

// ---------------- kernel pre: pre1[h][s] = W1R . cry[s] (fp16) ----------------
__global__ void __launch_bounds__(256, 1)
k_pre(const float* __restrict__ cry, const float* __restrict__ Wa1) {
    extern __shared__ unsigned smem_u[];
    unsigned* sA = smem_u;              // cry tile
    unsigned* sB = sA + 128 * LH2;      // W1R

    const int tid  = threadIdx.x;
    const int lane = tid & 31;
    const int warp = tid >> 5;
    const int warpRow = warp >> 1, warpCol = warp & 1;
    const int g = lane >> 2, t = lane & 3;
    const int h  = blockIdx.y;
    const int s0 = blockIdx.x * 128;

    load_w_h(sB, Wa1 + (size_t)h * 128 * 256 + 128, 256, tid);
    load_w_h(sA, cry + (size_t)s0 * 128, 128, tid);
    __syncthreads();

    float acc[2][8][4];
#pragma unroll
    for (int x1 = 0; x1 < 2; x1++)
#pragma unroll
        for (int x2 = 0; x2 < 8; x2++)
#pragma unroll
            for (int x3 = 0; x3 < 4; x3++) acc[x1][x2][x3] = 0.f;
    gemm128h(sA, sB, acc, warpRow, warpCol, g, t);

#pragma unroll
    for (int mt = 0; mt < 2; mt++)
#pragma unroll
        for (int nt = 0; nt < 8; nt++)
#pragma unroll
            for (int j = 0; j < 2; j++) {
                int row = warpRow * 32 + mt * 16 + g + j * 8;
                int c0  = warpCol * 64 + nt * 8 + 2 * t;
                g_pre1[((size_t)h * SEGS + s0 + row) * 64 + (c0 >> 1)] =
                    h2pack(acc[mt][nt][j * 2 + 0], acc[mt][nt][j * 2 + 1]);
            }
}

// ---------------- kernel 1: alpha (single GEMM + gathered pre1) ----------------
__global__ void __launch_bounds__(256, 2)
k_alpha(const float* __restrict__ fea,
        const float* __restrict__ Wa1, const float* __restrict__ ba1,
        const float* __restrict__ Wa2, const float* __restrict__ ba2,
        const int* __restrict__ index) {
    extern __shared__ unsigned smem_u[];
    unsigned* sA   = smem_u;                  // fea tile
    unsigned* sB1  = sA + 128 * LH2;          // W1L
    unsigned* sPre = sB1 + 128 * LH2;         // gathered pre1 (fp16), stride LH2
    float* sb1   = (float*)(sPre + 128 * LH2);
    float* sw2   = sb1 + 128;
    float* sPart = sw2 + 128;                 // 256
    int*   sSeg  = (int*)(sPart + 256);       // 128

    const int tid  = threadIdx.x;
    const int lane = tid & 31;
    const int warp = tid >> 5;
    const int warpRow = warp >> 1, warpCol = warp & 1;
    const int g = lane >> 2, t = lane & 3;
    const int h = blockIdx.y;

    load_w_h(sB1, Wa1 + (size_t)h * 128 * 256, 256, tid);
    if (tid < 128) {
        sb1[tid] = ba1[h * 128 + tid];
        sw2[tid] = Wa2[h * 128 + tid];
    }
    const float ba2v = ba2[h];
    const unsigned sPreAddr = (unsigned)__cvta_generic_to_shared(sPre);
    const unsigned* preH = g_pre1 + (size_t)h * SEGS * 64;
    __syncthreads();

    for (int tile = blockIdx.x; tile < NTILES; tile += gridDim.x) {
        const int row0 = tile * 128;
        const int rows = min(128, N_NODES - row0);

        if (tid < 128) sSeg[tid] = (tid < rows) ? index[row0 + tid] : 0;
        load_rows_h(sA, fea + (size_t)row0 * 128, rows, tid);
        __syncthreads();

        // gather pre1 rows via cp.async (overlaps GEMM below)
#pragma unroll
        for (int i = 0; i < 8; i++) {
            int v = i * 256 + tid;
            int r = v >> 4, ch = v & 15;
            cpa16(sPreAddr + (unsigned)(r * LH2 + ch * 4) * 4,
                  preH + (size_t)sSeg[r] * 64 + ch * 4);
        }
        asm volatile("cp.async.commit_group;" ::: "memory");

        float acc[2][8][4];
#pragma unroll
        for (int x1 = 0; x1 < 2; x1++)
#pragma unroll
            for (int x2 = 0; x2 < 8; x2++)
#pragma unroll
                for (int x3 = 0; x3 < 4; x3++) acc[x1][x2][x3] = 0.f;
        gemm128h(sA, sB1, acc, warpRow, warpCol, g, t);

        asm volatile("cp.async.wait_group 0;" ::: "memory");
        __syncthreads();

        // alpha[r] = sum_o leaky(acc + pre[seg[r]][o] + b1[o]) * w2[o] + b2
        float p[2][2];
#pragma unroll
        for (int mt = 0; mt < 2; mt++) { p[mt][0] = 0.f; p[mt][1] = 0.f; }
#pragma unroll
        for (int mt = 0; mt < 2; mt++)
#pragma unroll
            for (int nt = 0; nt < 8; nt++) {
                const int c0 = warpCol * 64 + nt * 8 + 2 * t;
                const int rbase = warpRow * 32 + mt * 16 + g;
#pragma unroll
                for (int j = 0; j < 2; j++) {
                    unsigned pw = sPre[(rbase + j * 8) * LH2 + (c0 >> 1)];
                    float2 pf = __half22float2(*reinterpret_cast<__half2*>(&pw));
                    float x0 = acc[mt][nt][j * 2 + 0] + pf.x + sb1[c0];
                    float x1 = acc[mt][nt][j * 2 + 1] + pf.y + sb1[c0 + 1];
                    x0 = (x0 >= 0.f) ? x0 : SLOPE * x0;
                    x1 = (x1 >= 0.f) ? x1 : SLOPE * x1;
                    p[mt][j] += x0 * sw2[c0] + x1 * sw2[c0 + 1];
                }
            }
#pragma unroll
        for (int mt = 0; mt < 2; mt++)
#pragma unroll
            for (int j = 0; j < 2; j++) {
                float v = p[mt][j];
                v += __shfl_xor_sync(0xffffffffu, v, 1);
                v += __shfl_xor_sync(0xffffffffu, v, 2);
                if ((lane & 3) == 0)
                    sPart[(warpRow * 32 + mt * 16 + g + j * 8) * 2 + warpCol] = v;
            }
        __syncthreads();
        if (tid < rows)
            g_alpha[(size_t)(row0 + tid) * 4 + h] = sPart[tid * 2] + sPart[tid * 2 + 1] + ba2v;
        __syncthreads();
    }
}

// ---------------- kernels 2/3: softmax stats ----------------
__device__ __forceinline__ unsigned f2key(float f) {
    unsigned b = __float_as_uint(f);
    return (b & 0x80000000u) ? ~b : (b | 0x80000000u);
}
__device__ __forceinline__ float key2f(unsigned k) {
    return __uint_as_float((k & 0x80000000u) ? (k & 0x7fffffffu) : ~k);
}

__global__ void k_max(const int* __restrict__ index) {
    int i = blockIdx.x * blockDim.x + threadIdx.x;
    if (i >= N_NODES * HEADS) return;
    int n = i >> 2, h = i & 3;
    atomicMax(&g_amax[index[n] * 4 + h], f2key(g_alpha[i]));
}

__global__ void k_exp(const int* __restrict__ index) {
    int i = blockIdx.x * blockDim.x + threadIdx.x;
    if (i >= N_NODES * HEADS) return;
    int n = i >> 2, h = i & 3;
    int s = index[n] * 4 + h;
    float amax = key2f(g_amax[s]);
    float e = expf(g_alpha[i] - amax);
    g_e[i] = e;
    atomicAdd(&g_denom[s], e);
}

// ---------------- kernel 4: message MLP + weighted scatter-add (R3 body) -----
__global__ void __launch_bounds__(256, 1)
k_msg(const float* __restrict__ fea,
      const float* __restrict__ Wm1, const float* __restrict__ bm1,
      const float* __restrict__ Wm2, const float* __restrict__ bm2,
      const int* __restrict__ index, float* __restrict__ out) {
    extern __shared__ unsigned smem_u[];
    unsigned* sA  = smem_u;
    unsigned* sB1 = sA + 128 * LH2;
    unsigned* sB2 = sB1 + 128 * LH2;
    float* sOut   = (float*)(sB2 + 128 * LH2);   // 128*LOUT
    float* sb1    = sOut + 128 * LOUT;
    float* sb2    = sb1 + 128;
    float* sScale = sb2 + 128;
    int*   sSeg   = (int*)(sScale + 128);

    const int tid  = threadIdx.x;
    const int lane = tid & 31;
    const int warp = tid >> 5;
    const int warpRow = warp >> 1, warpCol = warp & 1;
    const int g = lane >> 2, t = lane & 3;
    const int h = blockIdx.y;

    load_w_h(sB1, Wm1 + (size_t)h * 128 * 128, 128, tid);
    load_w_h(sB2, Wm2 + (size_t)h * 128 * 128, 128, tid);
    if (tid < 128) {
        sb1[tid] = bm1[h * 128 + tid];
        sb2[tid] = bm2[h * 128 + tid];
    }
    __syncthreads();

    for (int tile = blockIdx.x; tile < NTILES; tile += gridDim.x) {
        const int row0 = tile * 128;
        const int rows = min(128, N_NODES - row0);

        if (tid < 128) {
            if (tid < rows) {
                int s = index[row0 + tid];
                sSeg[tid] = s;
                sScale[tid] = g_e[(size_t)(row0 + tid) * 4 + h] /
                              (g_denom[s * 4 + h] + 1e-16f);
            } else {
                sSeg[tid] = index[row0 + rows - 1];
                sScale[tid] = 0.f;
            }
        }
        load_rows_h(sA, fea + (size_t)row0 * 128, rows, tid);
        __syncthreads();

        float acc[2][8][4];
#pragma unroll
        for (int x1 = 0; x1 < 2; x1++)
#pragma unroll
            for (int x2 = 0; x2 < 8; x2++)
#pragma unroll
                for (int x3 = 0; x3 < 4; x3++) acc[x1][x2][x3] = 0.f;
        gemm128h(sA, sB1, acc, warpRow, warpCol, g, t);
        __syncthreads();

        // hidden = leaky(acc + b1) -> sA as fp16
#pragma unroll
        for (int mt = 0; mt < 2; mt++)
#pragma unroll
            for (int nt = 0; nt < 8; nt++)
#pragma unroll
                for (int ip = 0; ip < 2; ip++) {
                    int row = warpRow * 32 + mt * 16 + g + ip * 8;
                    int c0 = warpCol * 64 + nt * 8 + 2 * t;
                    float x0 = acc[mt][nt][ip * 2 + 0] + sb1[c0];
                    float x1 = acc[mt][nt][ip * 2 + 1] + sb1[c0 + 1];
                    x0 = (x0 >= 0.f) ? x0 : SLOPE * x0;
                    x1 = (x1 >= 0.f) ? x1 : SLOPE * x1;
                    sA[row * LH2 + warpCol * 32 + nt * 4 + t] = h2pack(x0, x1);
                }
        __syncthreads();

#pragma unroll
        for (int x1 = 0; x1 < 2; x1++)
#pragma unroll
            for (int x2 = 0; x2 < 8; x2++)
#pragma unroll
                for (int x3 = 0; x3 < 4; x3++) acc[x1][x2][x3] = 0.f;
        gemm128h(sA, sB2, acc, warpRow, warpCol, g, t);

        // m*alpha -> sOut (fp32)
#pragma unroll
        for (int mt = 0; mt < 2; mt++)
#pragma unroll
            for (int nt = 0; nt < 8; nt++)
#pragma unroll
                for (int ip = 0; ip < 2; ip++) {
                    int row = warpRow * 32 + mt * 16 + g + ip * 8;
                    int c0 = warpCol * 64 + nt * 8 + 2 * t;
                    float sc = sScale[row];
                    float2 v;
                    v.x = (acc[mt][nt][ip * 2 + 0] + sb2[c0]) * sc;
                    v.y = (acc[mt][nt][ip * 2 + 1] + sb2[c0 + 1]) * sc;
                    *reinterpret_cast<float2*>(sOut + row * LOUT + c0) = v;
                }
        __syncthreads();

        // segmented reduce (sorted index): thread = column, two row-halves
        {
            const int c = tid & 127;
            const int r0 = (tid >> 7) * 64;
            float accum = 0.f;
            int cur = sSeg[r0];
            for (int r = r0; r < r0 + 64; r++) {
                int s = sSeg[r];
                if (s != cur) {
                    atomicAdd(&out[(size_t)cur * 512 + h * 128 + c], accum);
                    accum = 0.f;
                    cur = s;
                }
                accum += sOut[r * LOUT + c];
            }
            atomicAdd(&out[(size_t)cur * 512 + h * 128 + c], accum);
        }
        __syncthreads();
    }
}

// ---------------- launch ----------------
extern "C" void kernel_launch(void* const* d_in, const int* in_sizes, int n_in,
                              void* d_out, int out_size) {
    (void)in_sizes; (void)n_in;
    const float* fea = (const float*)d_in[0];
    const float* cry = (const float*)d_in[1];
    const float* Wm1 = (const float*)d_in[2];
    const float* bm1 = (const float*)d_in[3];
    const float* Wm2 = (const float*)d_in[4];
    const float* bm2 = (const float*)d_in[5];
    const float* Wa1 = (const float*)d_in[6];
    const float* ba1 = (const float*)d_in[7];
    const float* Wa2 = (const float*)d_in[8];
    const float* ba2 = (const float*)d_in[9];
    const int*   idx = (const int*)d_in[10];
    float* out = (float*)d_out;

    const size_t smem_pre   = (size_t)(2 * 128 * LH2) * 4;
    const size_t smem_alpha = (size_t)(3 * 128 * LH2 + 128 + 128 + 256 + 128) * 4;
    const size_t smem_msg   = (size_t)(3 * 128 * LH2 + 128 * LOUT + 128 + 128 + 128 + 128) * 4;
    cudaFuncSetAttribute(k_pre,   cudaFuncAttributeMaxDynamicSharedMemorySize, (int)smem_pre);
    cudaFuncSetAttribute(k_alpha, cudaFuncAttributeMaxDynamicSharedMemorySize, (int)smem_alpha);
    cudaFuncSetAttribute(k_msg,   cudaFuncAttributeMaxDynamicSharedMemorySize, (int)smem_msg);

    k_init<<<2048, 512>>>(out, out_size);
    k_pre<<<dim3(SEGS / 128, 4), 256, smem_pre>>>(cry, Wa1);
    k_alpha<<<dim3(74, 4), 256, smem_alpha>>>(fea, Wa1, ba1, Wa2, ba2, idx);
    int total = N_NODES * HEADS;
    k_max<<<(total + 255) / 256, 256>>>(idx);
    k_exp<<<(total + 255) / 256, 256>>>(idx);
    k_msg<<<dim3(37, 4), 256, smem_msg>>>(fea, Wm1, bm1, Wm2, bm2, idx, out);
}

// round 8
// speedup vs baseline: 1.0071x; 1.0071x over previous
#include <cuda_runtime.h>
#include <cuda_fp16.h>
#include <cstdint>

#define N_NODES 200000
#define SEGS    16384
#define NTILES  ((N_NODES + 127) / 128)   // 1563
#define HEADS   4
#define LH2     68     // smem row stride in half2 units
#define LOUT    132    // f32 out-tile stride
#define SLOPE   0.01f

// ---------------- device scratch ----------------
__device__ float    g_alpha[N_NODES * HEADS];
__device__ float    g_e[N_NODES * HEADS];
__device__ unsigned g_amax[SEGS * HEADS];
__device__ float    g_denom[SEGS * HEADS];
__device__ unsigned g_pre1[HEADS * SEGS * 64];   // fp16x2: W1R . cry  per segment

// ---------------- helpers ----------------
__device__ __forceinline__ unsigned h2pack(float a, float b) {
    unsigned r;
    asm("cvt.rn.f16x2.f32 %0, %2, %1;" : "=r"(r) : "f"(a), "f"(b));
    return r;  // lo = a, hi = b
}

__device__ __forceinline__ void mma_f16(float c[4], const unsigned a[4], const unsigned b[2]) {
    asm volatile(
        "mma.sync.aligned.m16n8k16.row.col.f32.f16.f16.f32 "
        "{%0,%1,%2,%3}, {%4,%5,%6,%7}, {%8,%9}, {%0,%1,%2,%3};\n"
        : "+f"(c[0]), "+f"(c[1]), "+f"(c[2]), "+f"(c[3])
        : "r"(a[0]), "r"(a[1]), "r"(a[2]), "r"(a[3]), "r"(b[0]), "r"(b[1]));
}

__device__ __forceinline__ void cpa16(unsigned saddr, const void* g) {
    asm volatile("cp.async.ca.shared.global [%0], [%1], 16;" :: "r"(saddr), "l"(g) : "memory");
}

// 128x128x128 GEMM: C[r][o] += sum_k A[r][k]*B[o][k]; fp16 half2-packed smem,
// row stride LH2. 8 warps (4x2), warp tile 32x64. (R3-proven scalar-LDS feed.)
__device__ __forceinline__ void gemm128h(const unsigned* sA, const unsigned* sB,
                                         float (&acc)[2][8][4],
                                         int warpRow, int warpCol, int g, int t) {
#pragma unroll 4
    for (int ks = 0; ks < 8; ks++) {
        const int k0 = ks * 8;
        unsigned a[2][4], b[8][2];
#pragma unroll
        for (int mt = 0; mt < 2; mt++) {
            int r = warpRow * 32 + mt * 16 + g;
            a[mt][0] = sA[r * LH2 + k0 + t];
            a[mt][1] = sA[(r + 8) * LH2 + k0 + t];
            a[mt][2] = sA[r * LH2 + k0 + t + 4];
            a[mt][3] = sA[(r + 8) * LH2 + k0 + t + 4];
        }
#pragma unroll
        for (int nt = 0; nt < 8; nt++) {
            int o = warpCol * 64 + nt * 8 + g;
            b[nt][0] = sB[o * LH2 + k0 + t];
            b[nt][1] = sB[o * LH2 + k0 + t + 4];
        }
#pragma unroll
        for (int mt = 0; mt < 2; mt++)
#pragma unroll
            for (int nt = 0; nt < 8; nt++)
                mma_f16(acc[mt][nt], a[mt], b[nt]);
    }
}

// load [rows<=128,128] f32 -> fp16 smem tile (256 threads)
__device__ __forceinline__ void load_rows_h(unsigned* dst, const float* __restrict__ src,
                                            int rows, int tid) {
#pragma unroll
    for (int i = 0; i < 16; i++) {
        int v = i * 256 + tid;
        int r = v >> 5, c4 = v & 31;
        float4 val = make_float4(0.f, 0.f, 0.f, 0.f);
        if (r < rows) val = reinterpret_cast<const float4*>(src)[r * 32 + c4];
        uint2 u = make_uint2(h2pack(val.x, val.y), h2pack(val.z, val.w));
        *reinterpret_cast<uint2*>(dst + r * LH2 + c4 * 2) = u;
    }
}

__device__ __forceinline__ void load_w_h(unsigned* dst, const float* __restrict__ src,
                                         int srcStride, int tid) {
#pragma unroll
    for (int i = 0; i < 16; i++) {
        int v = i * 256 + tid;
        int r = v >> 5, c4 = v & 31;
        float4 val = *reinterpret_cast<const float4*>(src + (size_t)r * srcStride + c4 * 4);
        uint2 u = make_uint2(h2pack(val.x, val.y), h2pack(val.z, val.w));
        *reinterpret_cast<uint2*>(dst + r * LH2 + c4 * 2) = u;
    }
}

// ---------------- kernel 0: init ----------------
__global__ void k_init(float* __restrict__ out, int out_size) {
    int i = blockIdx.x * blockDim.x + threadIdx.x;
    int stride = gridDim.x * blockDim.x;
    int n4 = out_size >> 2;
    for (int j = i; j < n4; j += stride)
        reinterpret_cast<float4*>(out)[j] = make_float4(0.f, 0.f, 0.f, 0.f);
    for (int j = n4 * 4 + i; j < out_size; j += stride) out[j] = 0.f;
    for (int j = i; j < SEGS * HEADS; j += stride) {
        g_amax[j] = 0u;
        g_denom[j] = 0.f;
    }
}

// ---------------- kernel pre: pre1[h][s] = W1R . cry[s] (fp16) ----------------
__global__ void __launch_bounds__(256, 1)
k_pre(const float* __restrict__ cry, const float* __restrict__ Wa1) {
    extern __shared__ unsigned smem_u[];
    unsigned* sA = smem_u;              // cry tile
    unsigned* sB = sA + 128 * LH2;      // W1R

    const int tid  = threadIdx.x;
    const int lane = tid & 31;
    const int warp = tid >> 5;
    const int warpRow = warp >> 1, warpCol = warp & 1;
    const int g = lane >> 2, t = lane & 3;
    const int h  = blockIdx.y;
    const int s0 = blockIdx.x * 128;

    load_w_h(sB, Wa1 + (size_t)h * 128 * 256 + 128, 256, tid);
    load_w_h(sA, cry + (size_t)s0 * 128, 128, tid);
    __syncthreads();

    float acc[2][8][4];
#pragma unroll
    for (int x1 = 0; x1 < 2; x1++)
#pragma unroll
        for (int x2 = 0; x2 < 8; x2++)
#pragma unroll
            for (int x3 = 0; x3 < 4; x3++) acc[x1][x2][x3] = 0.f;
    gemm128h(sA, sB, acc, warpRow, warpCol, g, t);

#pragma unroll
    for (int mt = 0; mt < 2; mt++)
#pragma unroll
        for (int nt = 0; nt < 8; nt++)
#pragma unroll
            for (int j = 0; j < 2; j++) {
                int row = warpRow * 32 + mt * 16 + g + j * 8;
                int c0  = warpCol * 64 + nt * 8 + 2 * t;
                g_pre1[((size_t)h * SEGS + s0 + row) * 64 + (c0 >> 1)] =
                    h2pack(acc[mt][nt][j * 2 + 0], acc[mt][nt][j * 2 + 1]);
            }
}

// ---------------- kernel 1: alpha (single GEMM + gathered pre1) ----------------
__global__ void __launch_bounds__(256, 2)
k_alpha(const float* __restrict__ fea,
        const float* __restrict__ Wa1, const float* __restrict__ ba1,
        const float* __restrict__ Wa2, const float* __restrict__ ba2,
        const int* __restrict__ index) {
    extern __shared__ unsigned smem_u[];
    unsigned* sA   = smem_u;                  // fea tile
    unsigned* sB1  = sA + 128 * LH2;          // W1L
    unsigned* sPre = sB1 + 128 * LH2;         // gathered pre1 (fp16), stride LH2
    float* sb1   = (float*)(sPre + 128 * LH2);
    float* sw2   = sb1 + 128;
    float* sPart = sw2 + 128;                 // 256
    int*   sSeg  = (int*)(sPart + 256);       // 128

    const int tid  = threadIdx.x;
    const int lane = tid & 31;
    const int warp = tid >> 5;
    const int warpRow = warp >> 1, warpCol = warp & 1;
    const int g = lane >> 2, t = lane & 3;
    const int h = blockIdx.y;

    load_w_h(sB1, Wa1 + (size_t)h * 128 * 256, 256, tid);
    if (tid < 128) {
        sb1[tid] = ba1[h * 128 + tid];
        sw2[tid] = Wa2[h * 128 + tid];
    }
    const float ba2v = ba2[h];
    const unsigned sPreAddr = (unsigned)__cvta_generic_to_shared(sPre);
    const unsigned* preH = g_pre1 + (size_t)h * SEGS * 64;
    __syncthreads();

    for (int tile = blockIdx.x; tile < NTILES; tile += gridDim.x) {
        const int row0 = tile * 128;
        const int rows = min(128, N_NODES - row0);

        if (tid < 128) sSeg[tid] = (tid < rows) ? index[row0 + tid] : 0;
        load_rows_h(sA, fea + (size_t)row0 * 128, rows, tid);
        __syncthreads();

        // gather pre1 rows via cp.async (overlaps GEMM below)
#pragma unroll
        for (int i = 0; i < 8; i++) {
            int v = i * 256 + tid;
            int r = v >> 4, ch = v & 15;
            cpa16(sPreAddr + (unsigned)(r * LH2 + ch * 4) * 4,
                  preH + (size_t)sSeg[r] * 64 + ch * 4);
        }
        asm volatile("cp.async.commit_group;" ::: "memory");

        float acc[2][8][4];
#pragma unroll
        for (int x1 = 0; x1 < 2; x1++)
#pragma unroll
            for (int x2 = 0; x2 < 8; x2++)
#pragma unroll
                for (int x3 = 0; x3 < 4; x3++) acc[x1][x2][x3] = 0.f;
        gemm128h(sA, sB1, acc, warpRow, warpCol, g, t);

        asm volatile("cp.async.wait_group 0;" ::: "memory");
        __syncthreads();

        // alpha[r] = sum_o leaky(acc + pre[seg[r]][o] + b1[o]) * w2[o] + b2
        float p[2][2];
#pragma unroll
        for (int mt = 0; mt < 2; mt++) { p[mt][0] = 0.f; p[mt][1] = 0.f; }
#pragma unroll
        for (int mt = 0; mt < 2; mt++)
#pragma unroll
            for (int nt = 0; nt < 8; nt++) {
                const int c0 = warpCol * 64 + nt * 8 + 2 * t;
                const int rbase = warpRow * 32 + mt * 16 + g;
#pragma unroll
                for (int j = 0; j < 2; j++) {
                    unsigned pw = sPre[(rbase + j * 8) * LH2 + (c0 >> 1)];
                    float2 pf = __half22float2(*reinterpret_cast<__half2*>(&pw));
                    float x0 = acc[mt][nt][j * 2 + 0] + pf.x + sb1[c0];
                    float x1 = acc[mt][nt][j * 2 + 1] + pf.y + sb1[c0 + 1];
                    x0 = (x0 >= 0.f) ? x0 : SLOPE * x0;
                    x1 = (x1 >= 0.f) ? x1 : SLOPE * x1;
                    p[mt][j] += x0 * sw2[c0] + x1 * sw2[c0 + 1];
                }
            }
#pragma unroll
        for (int mt = 0; mt < 2; mt++)
#pragma unroll
            for (int j = 0; j < 2; j++) {
                float v = p[mt][j];
                v += __shfl_xor_sync(0xffffffffu, v, 1);
                v += __shfl_xor_sync(0xffffffffu, v, 2);
                if ((lane & 3) == 0)
                    sPart[(warpRow * 32 + mt * 16 + g + j * 8) * 2 + warpCol] = v;
            }
        __syncthreads();
        if (tid < rows)
            g_alpha[(size_t)(row0 + tid) * 4 + h] = sPart[tid * 2] + sPart[tid * 2 + 1] + ba2v;
        __syncthreads();
    }
}

// ---------------- kernels 2/3: softmax stats ----------------
__device__ __forceinline__ unsigned f2key(float f) {
    unsigned b = __float_as_uint(f);
    return (b & 0x80000000u) ? ~b : (b | 0x80000000u);
}
__device__ __forceinline__ float key2f(unsigned k) {
    return __uint_as_float((k & 0x80000000u) ? (k & 0x7fffffffu) : ~k);
}

__global__ void k_max(const int* __restrict__ index) {
    int i = blockIdx.x * blockDim.x + threadIdx.x;
    if (i >= N_NODES * HEADS) return;
    int n = i >> 2, h = i & 3;
    atomicMax(&g_amax[index[n] * 4 + h], f2key(g_alpha[i]));
}

__global__ void k_exp(const int* __restrict__ index) {
    int i = blockIdx.x * blockDim.x + threadIdx.x;
    if (i >= N_NODES * HEADS) return;
    int n = i >> 2, h = i & 3;
    int s = index[n] * 4 + h;
    float amax = key2f(g_amax[s]);
    float e = expf(g_alpha[i] - amax);
    g_e[i] = e;
    atomicAdd(&g_denom[s], e);
}

// ---------------- kernel 4: message MLP + weighted scatter-add (R3 body) -----
__global__ void __launch_bounds__(256, 1)
k_msg(const float* __restrict__ fea,
      const float* __restrict__ Wm1, const float* __restrict__ bm1,
      const float* __restrict__ Wm2, const float* __restrict__ bm2,
      const int* __restrict__ index, float* __restrict__ out) {
    extern __shared__ unsigned smem_u[];
    unsigned* sA  = smem_u;
    unsigned* sB1 = sA + 128 * LH2;
    unsigned* sB2 = sB1 + 128 * LH2;
    float* sOut   = (float*)(sB2 + 128 * LH2);   // 128*LOUT
    float* sb1    = sOut + 128 * LOUT;
    float* sb2    = sb1 + 128;
    float* sScale = sb2 + 128;
    int*   sSeg   = (int*)(sScale + 128);

    const int tid  = threadIdx.x;
    const int lane = tid & 31;
    const int warp = tid >> 5;
    const int warpRow = warp >> 1, warpCol = warp & 1;
    const int g = lane >> 2, t = lane & 3;
    const int h = blockIdx.y;

    load_w_h(sB1, Wm1 + (size_t)h * 128 * 128, 128, tid);
    load_w_h(sB2, Wm2 + (size_t)h * 128 * 128, 128, tid);
    if (tid < 128) {
        sb1[tid] = bm1[h * 128 + tid];
        sb2[tid] = bm2[h * 128 + tid];
    }
    __syncthreads();

    for (int tile = blockIdx.x; tile < NTILES; tile += gridDim.x) {
        const int row0 = tile * 128;
        const int rows = min(128, N_NODES - row0);

        if (tid < 128) {
            if (tid < rows) {
                int s = index[row0 + tid];
                sSeg[tid] = s;
                sScale[tid] = g_e[(size_t)(row0 + tid) * 4 + h] /
                              (g_denom[s * 4 + h] + 1e-16f);
            } else {
                sSeg[tid] = index[row0 + rows - 1];
                sScale[tid] = 0.f;
            }
        }
        load_rows_h(sA, fea + (size_t)row0 * 128, rows, tid);
        __syncthreads();

        float acc[2][8][4];
#pragma unroll
        for (int x1 = 0; x1 < 2; x1++)
#pragma unroll
            for (int x2 = 0; x2 < 8; x2++)
#pragma unroll
                for (int x3 = 0; x3 < 4; x3++) acc[x1][x2][x3] = 0.f;
        gemm128h(sA, sB1, acc, warpRow, warpCol, g, t);
        __syncthreads();

        // hidden = leaky(acc + b1) -> sA as fp16
#pragma unroll
        for (int mt = 0; mt < 2; mt++)
#pragma unroll
            for (int nt = 0; nt < 8; nt++)
#pragma unroll
                for (int ip = 0; ip < 2; ip++) {
                    int row = warpRow * 32 + mt * 16 + g + ip * 8;
                    int c0 = warpCol * 64 + nt * 8 + 2 * t;
                    float x0 = acc[mt][nt][ip * 2 + 0] + sb1[c0];
                    float x1 = acc[mt][nt][ip * 2 + 1] + sb1[c0 + 1];
                    x0 = (x0 >= 0.f) ? x0 : SLOPE * x0;
                    x1 = (x1 >= 0.f) ? x1 : SLOPE * x1;
                    sA[row * LH2 + warpCol * 32 + nt * 4 + t] = h2pack(x0, x1);
                }
        __syncthreads();

#pragma unroll
        for (int x1 = 0; x1 < 2; x1++)
#pragma unroll
            for (int x2 = 0; x2 < 8; x2++)
#pragma unroll
                for (int x3 = 0; x3 < 4; x3++) acc[x1][x2][x3] = 0.f;
        gemm128h(sA, sB2, acc, warpRow, warpCol, g, t);

        // m*alpha -> sOut (fp32)
#pragma unroll
        for (int mt = 0; mt < 2; mt++)
#pragma unroll
            for (int nt = 0; nt < 8; nt++)
#pragma unroll
                for (int ip = 0; ip < 2; ip++) {
                    int row = warpRow * 32 + mt * 16 + g + ip * 8;
                    int c0 = warpCol * 64 + nt * 8 + 2 * t;
                    float sc = sScale[row];
                    float2 v;
                    v.x = (acc[mt][nt][ip * 2 + 0] + sb2[c0]) * sc;
                    v.y = (acc[mt][nt][ip * 2 + 1] + sb2[c0 + 1]) * sc;
                    *reinterpret_cast<float2*>(sOut + row * LOUT + c0) = v;
                }
        __syncthreads();

        // segmented reduce (sorted index): thread = column, two row-halves
        {
            const int c = tid & 127;
            const int r0 = (tid >> 7) * 64;
            float accum = 0.f;
            int cur = sSeg[r0];
            for (int r = r0; r < r0 + 64; r++) {
                int s = sSeg[r];
                if (s != cur) {
                    atomicAdd(&out[(size_t)cur * 512 + h * 128 + c], accum);
                    accum = 0.f;
                    cur = s;
                }
                accum += sOut[r * LOUT + c];
            }
            atomicAdd(&out[(size_t)cur * 512 + h * 128 + c], accum);
        }
        __syncthreads();
    }
}

// ---------------- launch ----------------
extern "C" void kernel_launch(void* const* d_in, const int* in_sizes, int n_in,
                              void* d_out, int out_size) {
    (void)in_sizes; (void)n_in;
    const float* fea = (const float*)d_in[0];
    const float* cry = (const float*)d_in[1];
    const float* Wm1 = (const float*)d_in[2];
    const float* bm1 = (const float*)d_in[3];
    const float* Wm2 = (const float*)d_in[4];
    const float* bm2 = (const float*)d_in[5];
    const float* Wa1 = (const float*)d_in[6];
    const float* ba1 = (const float*)d_in[7];
    const float* Wa2 = (const float*)d_in[8];
    const float* ba2 = (const float*)d_in[9];
    const int*   idx = (const int*)d_in[10];
    float* out = (float*)d_out;

    const size_t smem_pre   = (size_t)(2 * 128 * LH2) * 4;
    const size_t smem_alpha = (size_t)(3 * 128 * LH2 + 128 + 128 + 256 + 128) * 4;
    const size_t smem_msg   = (size_t)(3 * 128 * LH2 + 128 * LOUT + 128 + 128 + 128 + 128) * 4;
    cudaFuncSetAttribute(k_pre,   cudaFuncAttributeMaxDynamicSharedMemorySize, (int)smem_pre);
    cudaFuncSetAttribute(k_alpha, cudaFuncAttributeMaxDynamicSharedMemorySize, (int)smem_alpha);
    cudaFuncSetAttribute(k_msg,   cudaFuncAttributeMaxDynamicSharedMemorySize, (int)smem_msg);

    k_init<<<2048, 512>>>(out, out_size);
    k_pre<<<dim3(SEGS / 128, 4), 256, smem_pre>>>(cry, Wa1);
    k_alpha<<<dim3(74, 4), 256, smem_alpha>>>(fea, Wa1, ba1, Wa2, ba2, idx);
    int total = N_NODES * HEADS;
    k_max<<<(total + 255) / 256, 256>>>(idx);
    k_exp<<<(total + 255) / 256, 256>>>(idx);
    k_msg<<<dim3(37, 4), 256, smem_msg>>>(fea, Wm1, bm1, Wm2, bm2, idx, out);
}